// round 1
// baseline (speedup 1.0000x reference)
#include <cuda_runtime.h>
#include <math.h>

#define VOCAB 32000
#define EMB   32
#define HID   8
#define SEQ   64
#define BATCH 64
#define NROWS (SEQ*BATCH)   /* 4096 */

// Scratch (device globals: allocation-free rule)
__device__ float g_A[2*SEQ*BATCH*10];   // per-dir, per-(t,b): [az, ar, ah0..7] from e-part
__device__ float g_h[NROWS*16];         // total_h: [t][b][dir*8+j]
__device__ float g_sum[NROWS];          // sum of exp(logit) per row

// ---------------------------------------------------------------------------
// Kernel 0: embedding gather + input-projection precompute (parallel part of GRU)
// cat = [h, e]; rows 8..39 of W multiply e -> precompute e-dots + bias.
// Also zeroes g_sum for this replay (runs first every launch).
// ---------------------------------------------------------------------------
__global__ __launch_bounds__(64) void k_pre(
    const int*   __restrict__ x,   const float* __restrict__ emb,
    const float* __restrict__ Wz1, const float* __restrict__ bz1,
    const float* __restrict__ Wr1, const float* __restrict__ br1,
    const float* __restrict__ Wh1, const float* __restrict__ bh1,
    const float* __restrict__ Wz2, const float* __restrict__ bz2,
    const float* __restrict__ Wr2, const float* __restrict__ br2,
    const float* __restrict__ Wh2, const float* __restrict__ bh2)
{
    int t = blockIdx.x, dir = blockIdx.y, b = threadIdx.x;
    int gid = (dir*SEQ + t)*BATCH + b;
    if (gid < NROWS) g_sum[gid] = 0.f;

    const float* Wz = dir ? Wz2 : Wz1;
    const float* Wr = dir ? Wr2 : Wr1;
    const float* Wh = dir ? Wh2 : Wh1;
    float az = (dir ? bz2 : bz1)[0];
    float ar = (dir ? br2 : br1)[0];
    const float* bh = dir ? bh2 : bh1;
    float ah[8];
    #pragma unroll
    for (int j = 0; j < 8; j++) ah[j] = bh[j];

    int idx = x[t*BATCH + b];
    const float* e = emb + (size_t)idx * EMB;
    float ev[32];
    #pragma unroll
    for (int k = 0; k < 8; k++) {
        float4 v4 = ((const float4*)e)[k];
        ev[4*k+0] = v4.x; ev[4*k+1] = v4.y; ev[4*k+2] = v4.z; ev[4*k+3] = v4.w;
    }
    #pragma unroll
    for (int k = 0; k < 32; k++) {
        float evk = ev[k];
        az += evk * Wz[8 + k];
        ar += evk * Wr[8 + k];
        #pragma unroll
        for (int j = 0; j < 8; j++) ah[j] += evk * Wh[(8 + k)*8 + j];
    }
    float* Ab = g_A + (size_t)((dir*SEQ + t)*10)*BATCH + b;
    Ab[0] = az;
    Ab[BATCH] = ar;
    #pragma unroll
    for (int j = 0; j < 8; j++) Ab[(2 + j)*BATCH] = ah[j];
}

// ---------------------------------------------------------------------------
// Kernel 1: the serial GRU recurrences. 128 threads = 2 dirs x 64 batches,
// each thread runs one recurrence with h-part weights (80 floats) in registers.
// Emits the PRE-update hidden state at each step (matches reference scan).
// ---------------------------------------------------------------------------
__global__ __launch_bounds__(128) void k_gru(
    const float* __restrict__ Wz1, const float* __restrict__ Wr1, const float* __restrict__ Wh1,
    const float* __restrict__ Wz2, const float* __restrict__ Wr2, const float* __restrict__ Wh2)
{
    int tid = threadIdx.x;
    int dir = tid >> 6, b = tid & 63;
    const float* Wz = dir ? Wz2 : Wz1;
    const float* Wr = dir ? Wr2 : Wr1;
    const float* Wh = dir ? Wh2 : Wh1;

    float wz[8], wr[8], wh[64];
    #pragma unroll
    for (int i = 0; i < 8; i++) { wz[i] = Wz[i]; wr[i] = Wr[i]; }
    #pragma unroll
    for (int i = 0; i < 64; i++) wh[i] = Wh[i];   // rows 0..7 (h-part), [i*8+j]

    float h[8];
    #pragma unroll
    for (int j = 0; j < 8; j++) h[j] = 0.f;

    for (int step = 0; step < SEQ; ++step) {
        int time = dir ? (SEQ - 1 - step) : step;
        // store pre-update h (this is what the reference scan emits)
        float* gh = g_h + (size_t)(time*BATCH + b)*16 + dir*8;
        #pragma unroll
        for (int j = 0; j < 8; j++) gh[j] = h[j];

        const float* A = g_A + (size_t)((dir*SEQ + time)*10)*BATCH + b;
        float zi = A[0], ri = A[BATCH];
        #pragma unroll
        for (int i = 0; i < 8; i++) { zi += h[i]*wz[i]; ri += h[i]*wr[i]; }
        float z = 1.f / (1.f + __expf(-zi));
        float r = 1.f / (1.f + __expf(-ri));
        float hc[8];
        #pragma unroll
        for (int j = 0; j < 8; j++) {
            float s = A[(2 + j)*BATCH];
            #pragma unroll
            for (int i = 0; i < 8; i++) s += (r*h[i]) * wh[i*8 + j];
            hc[j] = tanhf(s);
        }
        #pragma unroll
        for (int j = 0; j < 8; j++) h[j] += z * (hc[j] - h[j]);
    }
}

// ---------------------------------------------------------------------------
// Kernels 2a/2b: logits + log_softmax over V=32000.
// |logit| <= 4.25 (|h|<=1, |Wout|<=0.25) -> no max subtraction needed.
// Tiling: block = 64 rows x 1280 vocab entries; warp owns 8 rows; thread owns
// 4 consecutive v (float4) -> Wout element reused 8x from L1 per warp,
// 64x per block from L2. FMA-bound by design.
// ---------------------------------------------------------------------------
__global__ __launch_bounds__(256) void k_sumexp(
    const float* __restrict__ Wout, const float* __restrict__ bout)
{
    __shared__ float h_sh[64*16];
    int tid = threadIdx.x;
    int by  = blockIdx.y;
    ((float4*)h_sh)[tid] = ((const float4*)(g_h + (size_t)by*64*16))[tid];
    __syncthreads();

    int warp = tid >> 5, lane = tid & 31;
    const float* hrow = h_sh + warp*8*16;
    float part[8];
    #pragma unroll
    for (int r = 0; r < 8; r++) part[r] = 0.f;

    int vbase = blockIdx.x*1280 + lane*4;
    for (int it = 0; it < 10; ++it) {
        int v = vbase + it*128;
        float4 bo = *(const float4*)(bout + v);
        float4 acc[8];
        #pragma unroll
        for (int r = 0; r < 8; r++) acc[r] = bo;
        #pragma unroll
        for (int k = 0; k < 16; k++) {
            float4 wv = *(const float4*)(Wout + (size_t)k*VOCAB + v);
            #pragma unroll
            for (int r = 0; r < 8; r++) {
                float hk = hrow[r*16 + k];
                acc[r].x = fmaf(hk, wv.x, acc[r].x);
                acc[r].y = fmaf(hk, wv.y, acc[r].y);
                acc[r].z = fmaf(hk, wv.z, acc[r].z);
                acc[r].w = fmaf(hk, wv.w, acc[r].w);
            }
        }
        #pragma unroll
        for (int r = 0; r < 8; r++) {
            part[r] += __expf(acc[r].x) + __expf(acc[r].y)
                     + __expf(acc[r].z) + __expf(acc[r].w);
        }
    }
    #pragma unroll
    for (int r = 0; r < 8; r++) {
        float p = part[r];
        #pragma unroll
        for (int off = 16; off > 0; off >>= 1)
            p += __shfl_xor_sync(0xffffffffu, p, off);
        if (lane == 0) atomicAdd(&g_sum[by*64 + warp*8 + r], p);
    }
}

__global__ __launch_bounds__(256) void k_write(
    const float* __restrict__ Wout, const float* __restrict__ bout,
    float* __restrict__ out)
{
    __shared__ float h_sh[64*16];
    __shared__ float lse_sh[64];
    int tid = threadIdx.x;
    int by  = blockIdx.y;
    ((float4*)h_sh)[tid] = ((const float4*)(g_h + (size_t)by*64*16))[tid];
    if (tid < 64) lse_sh[tid] = __logf(g_sum[by*64 + tid]);
    __syncthreads();

    int warp = tid >> 5, lane = tid & 31;
    const float* hrow = h_sh + warp*8*16;
    float ls[8];
    #pragma unroll
    for (int r = 0; r < 8; r++) ls[r] = lse_sh[warp*8 + r];

    int row_base = by*64 + warp*8;
    int vbase = blockIdx.x*1280 + lane*4;
    for (int it = 0; it < 10; ++it) {
        int v = vbase + it*128;
        float4 bo = *(const float4*)(bout + v);
        float4 acc[8];
        #pragma unroll
        for (int r = 0; r < 8; r++) acc[r] = bo;
        #pragma unroll
        for (int k = 0; k < 16; k++) {
            float4 wv = *(const float4*)(Wout + (size_t)k*VOCAB + v);
            #pragma unroll
            for (int r = 0; r < 8; r++) {
                float hk = hrow[r*16 + k];
                acc[r].x = fmaf(hk, wv.x, acc[r].x);
                acc[r].y = fmaf(hk, wv.y, acc[r].y);
                acc[r].z = fmaf(hk, wv.z, acc[r].z);
                acc[r].w = fmaf(hk, wv.w, acc[r].w);
            }
        }
        #pragma unroll
        for (int r = 0; r < 8; r++) {
            float4 o;
            o.x = acc[r].x - ls[r];
            o.y = acc[r].y - ls[r];
            o.z = acc[r].z - ls[r];
            o.w = acc[r].w - ls[r];
            *(float4*)(out + (size_t)(row_base + r)*VOCAB + v) = o;
        }
    }
}

// ---------------------------------------------------------------------------
extern "C" void kernel_launch(void* const* d_in, const int* in_sizes, int n_in,
                              void* d_out, int out_size)
{
    const int*   x    = (const int*)  d_in[0];
    const float* emb  = (const float*)d_in[1];
    const float* Wz1  = (const float*)d_in[2];  const float* bz1 = (const float*)d_in[3];
    const float* Wr1  = (const float*)d_in[4];  const float* br1 = (const float*)d_in[5];
    const float* Wh1  = (const float*)d_in[6];  const float* bh1 = (const float*)d_in[7];
    const float* Wz2  = (const float*)d_in[8];  const float* bz2 = (const float*)d_in[9];
    const float* Wr2  = (const float*)d_in[10]; const float* br2 = (const float*)d_in[11];
    const float* Wh2  = (const float*)d_in[12]; const float* bh2 = (const float*)d_in[13];
    const float* Wout = (const float*)d_in[14]; const float* bout= (const float*)d_in[15];
    float* out = (float*)d_out;

    k_pre<<<dim3(SEQ, 2), BATCH>>>(x, emb, Wz1, bz1, Wr1, br1, Wh1, bh1,
                                   Wz2, bz2, Wr2, br2, Wh2, bh2);
    k_gru<<<1, 128>>>(Wz1, Wr1, Wh1, Wz2, Wr2, Wh2);
    k_sumexp<<<dim3(25, 64), 256>>>(Wout, bout);
    k_write <<<dim3(25, 64), 256>>>(Wout, bout, out);
}